// round 7
// baseline (speedup 1.0000x reference)
#include <cuda_runtime.h>
#include <cuda_bf16.h>
#include <math.h>

typedef __nv_bfloat16 bf16;

// ---------------- dims ----------------
#define BB   2
#define TT   2048
#define DD   768
#define NHH  12
#define NKVV 4
#define HDD  64
#define LL   6
#define VV   32000
#define DII  1536
#define NCC  64
#define CDD  128
#define ROWS (BB*TT)          // 4096
#define GATE_STRENGTH 0.001f
#define EXN  ((long)DD*DII)   // expert matrix elements = 1,179,648

// ---------------- fp32 scratch ----------------
__device__ float g_x [ROWS*DD];
__device__ float g_q [ROWS*NHH*HDD];
__device__ float g_k [ROWS*NKVV*HDD];
__device__ float g_v [ROWS*NKVV*HDD];
__device__ float g_eb[6L*ROWS*DII];    // gate/up GEMM outputs (PF uses slots 0,1)
__device__ float g_cv[BB*10];
__device__ float g_tw[LL*BB*3];
__device__ int   g_ti[LL*BB*3];

// ---------------- bf16 hi/lo activation planes ----------------
__device__ bf16 g_h_h [ROWS*DD],        g_h_l [ROWS*DD];
__device__ bf16 g_ao_h[ROWS*NHH*HDD],   g_ao_l[ROWS*NHH*HDD];
__device__ bf16 g_hd_h[ROWS*DII],       g_hd_l[ROWS*DII];       // PF hidden
__device__ bf16 g_mh_h[3L*ROWS*DII],    g_mh_l[3L*ROWS*DII];    // MoE hidden

// ---------------- bf16 hi/lo weight planes ([N][K] K-major) ----------------
__device__ bf16 g_wq_h[6L*768*768],  g_wq_l[6L*768*768];
__device__ bf16 g_wk_h[6L*768*256],  g_wk_l[6L*768*256];
__device__ bf16 g_wv_h[6L*768*256],  g_wv_l[6L*768*256];
__device__ bf16 g_wo_h[6L*768*768],  g_wo_l[6L*768*768];
__device__ bf16 g_pg_h[6L*768*1536], g_pg_l[6L*768*1536];
__device__ bf16 g_pu_h[6L*768*1536], g_pu_l[6L*768*1536];
__device__ bf16 g_pd_h[6L*1536*768], g_pd_l[6L*1536*768];
__device__ bf16 g_em_h[(long)VV*DD], g_em_l[(long)VV*DD];   // already [N][K]
__device__ bf16 g_hg_h[(long)VV*DD], g_hg_l[(long)VV*DD];
__device__ bf16 g_eg_h[36L*DD*DII],  g_eg_l[36L*DD*DII];
__device__ bf16 g_eu_h[36L*DD*DII],  g_eu_l[36L*DD*DII];
__device__ bf16 g_ed_h[36L*DD*DII],  g_ed_l[36L*DD*DII];

// ---------------- small helpers ----------------
__device__ __forceinline__ float block_reduce_sum_256(float v) {
    __shared__ float red[8];
    int t = threadIdx.x;
    #pragma unroll
    for (int off = 16; off; off >>= 1) v += __shfl_xor_sync(0xffffffffu, v, off);
    if ((t & 31) == 0) red[t >> 5] = v;
    __syncthreads();
    float tot = 0.f;
    #pragma unroll
    for (int i = 0; i < 8; i++) tot += red[i];
    return tot;
}

__device__ __forceinline__ void split1(float f, bf16& h, bf16& l) {
    h = __float2bfloat16_rn(f);
    l = __float2bfloat16_rn(f - __bfloat162float(h));
}

__device__ __forceinline__ void split2(float f0, float f1, unsigned& hi, unsigned& lo) {
    __nv_bfloat162 h = __floats2bfloat162_rn(f0, f1);
    float r0 = f0 - __bfloat162float(__low2bfloat16(h));
    float r1 = f1 - __bfloat162float(__high2bfloat16(h));
    __nv_bfloat162 l = __floats2bfloat162_rn(r0, r1);
    hi = *(unsigned*)&h;
    lo = *(unsigned*)&l;
}

__device__ __forceinline__ void mma16816(float* c, const unsigned* a, const unsigned* b) {
    asm volatile(
        "mma.sync.aligned.m16n8k16.row.col.f32.bf16.bf16.f32 "
        "{%0,%1,%2,%3}, {%4,%5,%6,%7}, {%8,%9}, {%0,%1,%2,%3};\n"
        : "+f"(c[0]), "+f"(c[1]), "+f"(c[2]), "+f"(c[3])
        : "r"(a[0]), "r"(a[1]), "r"(a[2]), "r"(a[3]), "r"(b[0]), "r"(b[1]));
}

__device__ __forceinline__ void ldsm_x4(unsigned& r0, unsigned& r1, unsigned& r2,
                                        unsigned& r3, unsigned addr) {
    asm volatile("ldmatrix.sync.aligned.m8n8.x4.shared.b16 {%0,%1,%2,%3}, [%4];\n"
                 : "=r"(r0), "=r"(r1), "=r"(r2), "=r"(r3) : "r"(addr));
}

__device__ __forceinline__ void cp16(unsigned dst, const void* src) {
    asm volatile("cp.async.cg.shared.global [%0], [%1], 16;\n" :: "r"(dst), "l"(src));
}
__device__ __forceinline__ void cp_commit() { asm volatile("cp.async.commit_group;\n"); }
__device__ __forceinline__ void cp_wait0()  { asm volatile("cp.async.wait_group 0;\n" ::: "memory"); }

// ---------------- weight converters ----------------
// plain convert (no transpose): src already [N][K]
__global__ void convw_kernel(const float* __restrict__ s, bf16* __restrict__ hi,
                             bf16* __restrict__ lo, long n) {
    long i = ((long)blockIdx.x * blockDim.x + threadIdx.x) * 4;
    if (i < n) {
        float4 v = *(const float4*)(s + i);
        unsigned h0, l0, h1, l1;
        split2(v.x, v.y, h0, l0);
        split2(v.z, v.w, h1, l1);
        *(uint2*)&hi[i] = make_uint2(h0, h1);
        *(uint2*)&lo[i] = make_uint2(l0, l1);
    }
}

// transpose-convert: src [K][N] fp32 -> dst [N][K] bf16 hi/lo.
// grid (N/32, K/32, nmats), block (32,8)
__global__ void convt_kernel(const float* __restrict__ src, bf16* __restrict__ hi,
                             bf16* __restrict__ lo, int K, int N, long mstride) {
    __shared__ float tile[32][33];
    const float* s = src + (long)blockIdx.z * mstride;
    bf16* h = hi + (long)blockIdx.z * mstride;
    bf16* l = lo + (long)blockIdx.z * mstride;
    int n0 = blockIdx.x * 32, k0 = blockIdx.y * 32;
    int tx = threadIdx.x, ty = threadIdx.y;
    #pragma unroll
    for (int i = ty; i < 32; i += 8)
        tile[i][tx] = s[(long)(k0 + i) * N + n0 + tx];
    __syncthreads();
    #pragma unroll
    for (int i = ty; i < 32; i += 8) {
        float v = tile[tx][i];
        bf16 hh, ll;
        split1(v, hh, ll);
        h[(long)(n0 + i) * K + k0 + tx] = hh;
        l[(long)(n0 + i) * K + k0 + tx] = ll;
    }
}

// expert transpose-convert with router indirection. grid (N/32, K/32, 36)
__global__ void convt_exp_kernel(const float* __restrict__ src, bf16* __restrict__ hi,
                                 bf16* __restrict__ lo, int K, int N,
                                 const int* __restrict__ ti) {
    __shared__ float tile[32][33];
    const int slot = blockIdx.z;
    const int l = slot / 6, e = ti[slot];
    const float* s = src + ((long)l * 10 + e) * EXN;
    bf16* h = hi + (long)slot * EXN;
    bf16* lw = lo + (long)slot * EXN;
    int n0 = blockIdx.x * 32, k0 = blockIdx.y * 32;
    int tx = threadIdx.x, ty = threadIdx.y;
    #pragma unroll
    for (int i = ty; i < 32; i += 8)
        tile[i][tx] = s[(long)(k0 + i) * N + n0 + tx];
    __syncthreads();
    #pragma unroll
    for (int i = ty; i < 32; i += 8) {
        float v = tile[tx][i];
        bf16 hh, ll;
        split1(v, hh, ll);
        h[(long)(n0 + i) * K + k0 + tx] = hh;
        lw[(long)(n0 + i) * K + k0 + tx] = ll;
    }
}

// ---------------- embedding ----------------
__global__ void embed_kernel(const int* __restrict__ idx,
                             const float* __restrict__ emb,
                             float* __restrict__ x) {
    long i = (long)blockIdx.x * blockDim.x + threadIdx.x;
    if (i < (long)ROWS * DD) {
        long r = i / DD, c = i % DD;
        x[i] = emb[(long)idx[r] * DD + c];
    }
}

// ---------------- consciousness vector (tiny MLP) ----------------
__global__ void cv_kernel(const float* __restrict__ cs,
                          const float* __restrict__ w1, const float* __restrict__ b1,
                          const float* __restrict__ w2, const float* __restrict__ b2,
                          float* __restrict__ cv) {
    __shared__ float pooled[BB][CDD];
    __shared__ float h1[BB][64];
    int t = threadIdx.x;  // 256 threads
    {
        int b = t / CDD, c = t % CDD;
        float s = 0.f;
        for (int n = 0; n < NCC; n++)
            s += cs[((long)b * NCC + n) * CDD + c];
        pooled[b][c] = s * (1.f / NCC);
    }
    __syncthreads();
    if (t < BB * 64) {
        int b = t / 64, j = t % 64;
        float z = b1[j];
        for (int c = 0; c < CDD; c++) z += pooled[b][c] * w1[c * 64 + j];
        float z3 = z * z * z;
        h1[b][j] = 0.5f * z * (1.f + tanhf(0.7978845608028654f * (z + 0.044715f * z3)));
    }
    __syncthreads();
    if (t < BB * 10) {
        int b = t / 10, i = t % 10;
        float z = b2[i];
        for (int j = 0; j < 64; j++) z += h1[b][j] * w2[j * 10 + i];
        cv[b * 10 + i] = 1.f / (1.f + expf(-z));
    }
}

// ---------------- routers for all layers ----------------
__global__ void router_all_kernel(const float* __restrict__ cv,
                                  const float* __restrict__ W,
                                  const float* __restrict__ bias,
                                  float* __restrict__ tw, int* __restrict__ ti) {
    int l = blockIdx.x;
    int b = threadIdx.x;
    if (b >= BB) return;
    const float* Wl = W + (long)l * 100;
    const float* bl = bias + (long)l * 10;
    float lg[10];
    float mx = -1e30f;
    for (int i = 0; i < 10; i++) {
        float z = bl[i];
        for (int j = 0; j < 10; j++) z += cv[b * 10 + j] * Wl[j * 10 + i];
        lg[i] = z;
        mx = fmaxf(mx, z);
    }
    float se = 0.f;
    for (int i = 0; i < 10; i++) { lg[i] = expf(lg[i] - mx); se += lg[i]; }
    for (int i = 0; i < 10; i++) lg[i] /= se;
    float wsum = 0.f;
    int base = l * 6 + b * 3;
    for (int kk = 0; kk < 3; kk++) {
        int bi = 0; float bv = -1.f;
        for (int i = 0; i < 10; i++) if (lg[i] > bv) { bv = lg[i]; bi = i; }
        ti[base + kk] = bi; tw[base + kk] = bv; wsum += bv;
        lg[bi] = -2.f;
    }
    for (int kk = 0; kk < 3; kk++) tw[base + kk] /= wsum;
}

// ---------------- RMSNorm -> bf16 hi/lo planes ----------------
__global__ void __launch_bounds__(256) rms_kernel(const float* __restrict__ x,
                                                  const float* __restrict__ w,
                                                  bf16* __restrict__ oh,
                                                  bf16* __restrict__ ol) {
    int row = blockIdx.x, t = threadIdx.x;
    const float* xr = x + (long)row * DD;
    float v0 = xr[t], v1 = xr[t + 256], v2 = xr[t + 512];
    float tot = block_reduce_sum_256(v0 * v0 + v1 * v1 + v2 * v2);
    float s = rsqrtf(tot * (1.f / DD) + 1e-6f);
    bf16* ohr = oh + (long)row * DD;
    bf16* olr = ol + (long)row * DD;
    split1(v0 * s * w[t],       ohr[t],       olr[t]);
    split1(v1 * s * w[t + 256], ohr[t + 256], olr[t + 256]);
    split1(v2 * s * w[t + 512], ohr[t + 512], olr[t + 512]);
}

// ---------------- SwiGLU (+ tension) -> bf16 planes ----------------
__global__ void __launch_bounds__(256) swiglu_kernel(const float* __restrict__ g,
                                                     const float* __restrict__ u,
                                                     bf16* __restrict__ oh,
                                                     bf16* __restrict__ ol,
                                                     float* __restrict__ tension) {
    int row = blockIdx.x, t = threadIdx.x;
    const float* gr = g + (long)row * DII;
    const float* ur = u + (long)row * DII;
    bf16* ohr = oh + (long)row * DII;
    bf16* olr = ol + (long)row * DII;
    float sum = 0.f;
    #pragma unroll
    for (int j = 0; j < 6; j++) {
        int c = t + j * 256;
        float a = gr[c], bv = ur[c];
        float hv = (a / (1.f + __expf(-a))) * bv;
        split1(hv, ohr[c], olr[c]);
        sum += hv;
    }
    float tot = block_reduce_sum_256(sum);
    if (t == 0) tension[row] = tanhf(tot * (1.f / DII));
}

// ---------------- MoE SwiGLU (folds router weight) -> bf16 planes --------------
__global__ void __launch_bounds__(256) swiglu_moe_kernel(const float* __restrict__ buf,
                                                         const float* __restrict__ tw,
                                                         bf16* __restrict__ mh,
                                                         bf16* __restrict__ ml) {
    int row = blockIdx.x, e = blockIdx.y, t = threadIdx.x;
    int b = row / TT;
    float scale = tw[b * 3 + e];
    const float* gr = buf + (long)(2 * e) * ROWS * DII + (long)row * DII;
    const float* ur = buf + (long)(2 * e + 1) * ROWS * DII + (long)row * DII;
    bf16* ohr = mh + (long)e * ROWS * DII + (long)row * DII;
    bf16* olr = ml + (long)e * ROWS * DII + (long)row * DII;
    #pragma unroll
    for (int j = 0; j < 6; j++) {
        int c = t + j * 256;
        float a = gr[c], bv = ur[c];
        split1((a / (1.f + __expf(-a))) * bv * scale, ohr[c], olr[c]);
    }
}

// ---------------- consciousness-state residual add ----------------
__global__ void __launch_bounds__(256) csadd_kernel(float* __restrict__ x,
                                                    const float* __restrict__ tension,
                                                    const float* __restrict__ tw) {
    int row = blockIdx.x, t = threadIdx.x;
    float ten = tension[row] * GATE_STRENGTH;
    float* xr = x + (long)row * DD;
    xr[t]       += ten * tw[t];
    xr[t + 256] += ten * tw[t + 256];
    xr[t + 512] += ten * tw[t + 512];
}

// ---------------- flash-style causal attention (fp32, GQA) ----------------
__global__ void __launch_bounds__(64) attn_kernel(const float* __restrict__ q,
                                                  const float* __restrict__ k,
                                                  const float* __restrict__ v,
                                                  bf16* __restrict__ oh,
                                                  bf16* __restrict__ ol) {
    const int q0 = blockIdx.x * 64;
    const int h  = blockIdx.y;
    const int b  = blockIdx.z;
    const int t  = threadIdx.x;
    const int qg = q0 + t;
    const int kvh = h / (NHH / NKVV);

    __shared__ float Ks[64][64];
    __shared__ float Vs[64][64];

    float qreg[64], acc[64];
    const float* qp = q + ((long)(b * TT + qg) * NHH + h) * HDD;
    #pragma unroll
    for (int d = 0; d < 64; d++) { qreg[d] = qp[d]; acc[d] = 0.f; }
    float lsum = 0.f;

    for (int s0 = 0; s0 <= q0; s0 += 64) {
        __syncthreads();
        #pragma unroll 8
        for (int r = 0; r < 64; r++) {
            long base = ((long)(b * TT + s0 + r) * NKVV + kvh) * HDD + t;
            Ks[r][t] = k[base];
            Vs[r][t] = v[base];
        }
        __syncthreads();
        int kmax = min(64, qg - s0 + 1);
        for (int kk = 0; kk < kmax; kk++) {
            float s = 0.f;
            #pragma unroll
            for (int d = 0; d < 64; d++) s += qreg[d] * Ks[kk][d];
            float p = __expf(s * 0.125f);
            lsum += p;
            #pragma unroll
            for (int d = 0; d < 64; d++) acc[d] += p * Vs[kk][d];
        }
    }
    float inv = 1.f / lsum;
    long base = ((long)(b * TT + qg) * NHH + h) * HDD;
    #pragma unroll
    for (int d = 0; d < 64; d += 2) {
        unsigned hi, lo;
        split2(acc[d] * inv, acc[d + 1] * inv, hi, lo);
        *(unsigned*)&oh[base + d] = hi;
        *(unsigned*)&ol[base + d] = lo;
    }
}

// ================= tensor-core GEMM (bf16x3, 64x64 warp tiles) =================
// C[M,N] = [C +] Ahi@Bhi^T + Ahi@Blo^T + Alo@Bhi^T   (B stored [N][K] K-major)
// 128x128 CTA tile, 4 warps (128 thr), warp tile 64x64, BK=32, double buffer,
// cp.async staging, 2 CTAs/SM.
// MODE 0: plain; optional paired problem (B2,C2) via blockIdx.z.
// MODE 1: MoE gate/up: z in [0,6): kexp=z>>1; planes = (z&1 ? B2 : B) +
//         (bb*3+kexp)*sstride; C += z*ROWS*N.
// MODE 2: MoE down: 3 K-segments; A seg s at +s*ROWS*K; B seg s at +(bb*3+s)*sstride.
#define PLN 10240           // bytes per plane (128 rows x 40 halfs)
#define STG 40960           // bytes per stage (4 planes)
#define GSM (2*STG)         // 81,920 dynamic smem

template<bool ACC, int MODE>
__global__ void __launch_bounds__(128, 2) gemm3(
    const bf16* __restrict__ Ah, const bf16* __restrict__ Al,
    const bf16* __restrict__ Bh, const bf16* __restrict__ Bl,
    float* __restrict__ C,
    const bf16* __restrict__ B2h, const bf16* __restrict__ B2l, float* __restrict__ C2,
    int M, int N, int K, long sstride)
{
    const int bx = blockIdx.x, by = blockIdx.y;
    const int bb = (by * 128) / TT;              // batch (tiles never straddle)
    if (MODE == 0) {
        if (B2h != nullptr && blockIdx.z == 1) { Bh = B2h; Bl = B2l; C = C2; }
    } else if (MODE == 1) {
        const int z = blockIdx.z, kexp = z >> 1;
        long off = (long)(bb * 3 + kexp) * sstride;
        if (z & 1) { Bh = B2h + off; Bl = B2l + off; }
        else       { Bh = Bh  + off; Bl = Bl  + off; }
        C += (long)z * ROWS * N;
    }
    const bf16 *Bsh[3], *Bsl[3];
    if (MODE == 2) {
        #pragma unroll
        for (int s = 0; s < 3; s++) {
            long off = (long)(bb * 3 + s) * sstride;
            Bsh[s] = Bh + off; Bsl[s] = Bl + off;
        }
    }

    extern __shared__ bf16 sm[];
    const unsigned su = (unsigned)__cvta_generic_to_shared(sm);

    const int tid = threadIdx.x;
    const int wid = tid >> 5, lane = tid & 31;
    const int g = lane >> 2, tq = lane & 3;
    const int m0 = (wid & 1) * 64, n0 = (wid >> 1) * 64;
    const int lrow = lane & 15, lcol = (lane >> 4) * 8;

    const int kIters = K >> 5;
    const int total  = (MODE == 2 ? 3 : 1) * kIters;

    const int q4 = tid & 3;        // 16B chunk within 64B row segment
    const int rg = tid >> 2;       // 0..31

    auto issue = [&](int it) {
        const int st  = it & 1;
        const int seg = (MODE == 2) ? it / kIters : 0;
        const int k0  = ((MODE == 2) ? (it % kIters) : it) * 32;
        const bf16* pAh = Ah + ((MODE == 2) ? (long)seg * ROWS * K : 0);
        const bf16* pAl = Al + ((MODE == 2) ? (long)seg * ROWS * K : 0);
        const bf16* pBh = (MODE == 2) ? Bsh[seg] : Bh;
        const bf16* pBl = (MODE == 2) ? Bsl[seg] : Bl;
        #pragma unroll
        for (int rr = 0; rr < 4; rr++) {
            const int r = rg + rr * 32;
            const long ga = (long)(by * 128 + r) * K + k0 + q4 * 8;
            const long gb = (long)(bx * 128 + r) * K + k0 + q4 * 8;
            const unsigned so = (unsigned)(st * STG) + (unsigned)r * 80u
                              + (unsigned)q4 * 16u;
            cp16(su + so,           pAh + ga);
            cp16(su + PLN + so,     pAl + ga);
            cp16(su + 2*PLN + so,   pBh + gb);
            cp16(su + 3*PLN + so,   pBl + gb);
        }
        cp_commit();
    };

    float acc[4][8][4];
    #pragma unroll
    for (int i = 0; i < 4; i++)
        #pragma unroll
        for (int j = 0; j < 8; j++)
            #pragma unroll
            for (int e = 0; e < 4; e++) acc[i][j][e] = 0.f;

    issue(0);

    for (int it = 0; it < total; it++) {
        const int st = it & 1;
        cp_wait0();
        __syncthreads();
        if (it + 1 < total) issue(it + 1);

        const unsigned base = su + (unsigned)(st * STG);
        #pragma unroll
        for (int ks = 0; ks < 2; ks++) {
            const int kk = ks * 16;
            // B fragments: 8 j-atoms, hi+lo
            unsigned bh[8][2], bl[8][2];
            #pragma unroll
            for (int jp = 0; jp < 4; jp++) {
                const unsigned off =
                    (unsigned)((n0 + jp * 16 + lrow) * 40 + kk + lcol) * 2u;
                unsigned r0, r1, r2, r3;
                ldsm_x4(r0, r1, r2, r3, base + 2*PLN + off);
                bh[2*jp][0] = r0; bh[2*jp+1][0] = r1;
                bh[2*jp][1] = r2; bh[2*jp+1][1] = r3;
                ldsm_x4(r0, r1, r2, r3, base + 3*PLN + off);
                bl[2*jp][0] = r0; bl[2*jp+1][0] = r1;
                bl[2*jp][1] = r2; bl[2*jp+1][1] = r3;
            }
            // A fragments per i, then 24 MMAs
            #pragma unroll
            for (int i = 0; i < 4; i++) {
                const unsigned off =
                    (unsigned)((m0 + i * 16 + lrow) * 40 + kk + lcol) * 2u;
                unsigned ah[4], al[4];
                ldsm_x4(ah[0], ah[1], ah[2], ah[3], base + off);
                ldsm_x4(al[0], al[1], al[2], al[3], base + PLN + off);
                #pragma unroll
                for (int j = 0; j < 8; j++) {
                    mma16816(acc[i][j], ah, bh[j]);
                    mma16816(acc[i][j], ah, bl[j]);
                    mma16816(acc[i][j], al, bh[j]);
                }
            }
        }
    }

    // ---- epilogue: direct fp32 stores ----
    #pragma unroll
    for (int i = 0; i < 4; i++) {
        const long r0 = (long)(by * 128 + m0 + i * 16 + g);
        const long r1 = r0 + 8;
        #pragma unroll
        for (int j = 0; j < 8; j++) {
            const long c = (long)(bx * 128 + n0 + j * 8 + 2 * tq);
            if (ACC) {
                C[r0 * N + c]     += acc[i][j][0];
                C[r0 * N + c + 1] += acc[i][j][1];
                C[r1 * N + c]     += acc[i][j][2];
                C[r1 * N + c + 1] += acc[i][j][3];
            } else {
                *(float2*)&C[r0 * N + c] = make_float2(acc[i][j][0], acc[i][j][1]);
                *(float2*)&C[r1 * N + c] = make_float2(acc[i][j][2], acc[i][j][3]);
            }
        }
    }
}

// ---------------- launch ----------------
extern "C" void kernel_launch(void* const* d_in, const int* in_sizes, int n_in,
                              void* d_out, int out_size) {
    const int*   idx       = (const int*)  d_in[0];
    const float* cons      = (const float*)d_in[1];
    const float* tok_emb   = (const float*)d_in[2];
    const float* head_g    = (const float*)d_in[3];
    const float* cv_w1     = (const float*)d_in[4];
    const float* cv_b1     = (const float*)d_in[5];
    const float* cv_w2     = (const float*)d_in[6];
    const float* cv_b2     = (const float*)d_in[7];
    const float* tension_w = (const float*)d_in[8];
    const float* ln_attn   = (const float*)d_in[9];
    const float* ln_pf     = (const float*)d_in[10];
    const float* ln_moe    = (const float*)d_in[11];
    const float* ln_f      = (const float*)d_in[12];
    const float* wq        = (const float*)d_in[13];
    const float* wk        = (const float*)d_in[14];
    const float* wv        = (const float*)d_in[15];
    const float* wo        = (const float*)d_in[16];
    const float* pf_gate   = (const float*)d_in[17];
    const float* pf_up     = (const float*)d_in[18];
    const float* pf_down   = (const float*)d_in[19];
    const float* e_gate    = (const float*)d_in[20];
    const float* e_up      = (const float*)d_in[21];
    const float* e_down    = (const float*)d_in[22];
    const float* router_w  = (const float*)d_in[23];
    const float* router_b  = (const float*)d_in[24];
    float* out = (float*)d_out;

    float *xp, *qp, *kp, *vp, *ebp, *cvp, *twp;  int* tip;
    bf16 *hh, *hl, *aoh, *aol, *hdh, *hdl, *mhh, *mhl;
    bf16 *wqh, *wql, *wkh, *wkl, *wvh, *wvl, *woh, *wol;
    bf16 *pgh, *pgl, *puh, *pul, *pdh, *pdl;
    bf16 *emh, *eml, *hgh, *hgl;
    bf16 *egh, *egl, *euh, *eul, *edh, *edl;
    cudaGetSymbolAddress((void**)&xp,  g_x);
    cudaGetSymbolAddress((void**)&qp,  g_q);
    cudaGetSymbolAddress((void**)&kp,  g_k);
    cudaGetSymbolAddress((void**)&vp,  g_v);
    cudaGetSymbolAddress((void**)&ebp, g_eb);
    cudaGetSymbolAddress((void**)&cvp, g_cv);
    cudaGetSymbolAddress((void**)&twp, g_tw);
    cudaGetSymbolAddress((void**)&tip, g_ti);
    cudaGetSymbolAddress((void**)&hh,  g_h_h);  cudaGetSymbolAddress((void**)&hl,  g_h_l);
    cudaGetSymbolAddress((void**)&aoh, g_ao_h); cudaGetSymbolAddress((void**)&aol, g_ao_l);
    cudaGetSymbolAddress((void**)&hdh, g_hd_h); cudaGetSymbolAddress((void**)&hdl, g_hd_l);
    cudaGetSymbolAddress((void**)&mhh, g_mh_h); cudaGetSymbolAddress((void**)&mhl, g_mh_l);
    cudaGetSymbolAddress((void**)&wqh, g_wq_h); cudaGetSymbolAddress((void**)&wql, g_wq_l);
    cudaGetSymbolAddress((void**)&wkh, g_wk_h); cudaGetSymbolAddress((void**)&wkl, g_wk_l);
    cudaGetSymbolAddress((void**)&wvh, g_wv_h); cudaGetSymbolAddress((void**)&wvl, g_wv_l);
    cudaGetSymbolAddress((void**)&woh, g_wo_h); cudaGetSymbolAddress((void**)&wol, g_wo_l);
    cudaGetSymbolAddress((void**)&pgh, g_pg_h); cudaGetSymbolAddress((void**)&pgl, g_pg_l);
    cudaGetSymbolAddress((void**)&puh, g_pu_h); cudaGetSymbolAddress((void**)&pul, g_pu_l);
    cudaGetSymbolAddress((void**)&pdh, g_pd_h); cudaGetSymbolAddress((void**)&pdl, g_pd_l);
    cudaGetSymbolAddress((void**)&emh, g_em_h); cudaGetSymbolAddress((void**)&eml, g_em_l);
    cudaGetSymbolAddress((void**)&hgh, g_hg_h); cudaGetSymbolAddress((void**)&hgl, g_hg_l);
    cudaGetSymbolAddress((void**)&egh, g_eg_h); cudaGetSymbolAddress((void**)&egl, g_eg_l);
    cudaGetSymbolAddress((void**)&euh, g_eu_h); cudaGetSymbolAddress((void**)&eul, g_eu_l);
    cudaGetSymbolAddress((void**)&edh, g_ed_h); cudaGetSymbolAddress((void**)&edl, g_ed_l);

    cudaFuncSetAttribute(gemm3<false, 0>, cudaFuncAttributeMaxDynamicSharedMemorySize, GSM);
    cudaFuncSetAttribute(gemm3<true,  0>, cudaFuncAttributeMaxDynamicSharedMemorySize, GSM);
    cudaFuncSetAttribute(gemm3<false, 1>, cudaFuncAttributeMaxDynamicSharedMemorySize, GSM);
    cudaFuncSetAttribute(gemm3<true,  2>, cudaFuncAttributeMaxDynamicSharedMemorySize, GSM);

    float* tens = out + (long)2 * ROWS * VV;   // output tail: tensions (L, B, T)
    float* b1p = ebp;
    float* b2p = ebp + (long)ROWS * DII;

    // ---- preprocessing ----
    embed_kernel<<<(ROWS * DD + 255) / 256, 256>>>(idx, tok_emb, xp);
    cv_kernel<<<1, 256>>>(cons, cv_w1, cv_b1, cv_w2, cv_b2, cvp);
    router_all_kernel<<<LL, 32>>>(cvp, router_w, router_b, twp, tip);

    const dim3 cb(32, 8);
    convt_kernel<<<dim3(768/32, 768/32, 6),  cb>>>(wq, wqh, wql, 768, 768,  768L*768);
    convt_kernel<<<dim3(256/32, 768/32, 6),  cb>>>(wk, wkh, wkl, 768, 256,  768L*256);
    convt_kernel<<<dim3(256/32, 768/32, 6),  cb>>>(wv, wvh, wvl, 768, 256,  768L*256);
    convt_kernel<<<dim3(768/32, 768/32, 6),  cb>>>(wo, woh, wol, 768, 768,  768L*768);
    convt_kernel<<<dim3(1536/32, 768/32, 6), cb>>>(pf_gate, pgh, pgl, 768, 1536, 768L*1536);
    convt_kernel<<<dim3(1536/32, 768/32, 6), cb>>>(pf_up,   puh, pul, 768, 1536, 768L*1536);
    convt_kernel<<<dim3(768/32, 1536/32, 6), cb>>>(pf_down, pdh, pdl, 1536, 768, 1536L*768);
    convw_kernel<<<(int)((long)VV*DD/4/256), 256>>>(tok_emb, emh, eml, (long)VV*DD);
    convw_kernel<<<(int)((long)VV*DD/4/256), 256>>>(head_g,  hgh, hgl, (long)VV*DD);
    convt_exp_kernel<<<dim3(1536/32, 768/32, 36), cb>>>(e_gate, egh, egl, 768, 1536, tip);
    convt_exp_kernel<<<dim3(1536/32, 768/32, 36), cb>>>(e_up,   euh, eul, 768, 1536, tip);
    convt_exp_kernel<<<dim3(768/32, 1536/32, 36), cb>>>(e_down, edh, edl, 1536, 768, tip);

    const dim3 gq  (768  / 128, ROWS / 128, 1);
    const dim3 gkv (256  / 128, ROWS / 128, 2);
    const dim3 gff (DII  / 128, ROWS / 128, 2);
    const dim3 gegu(DII  / 128, ROWS / 128, 6);
    const dim3 gdn (DD   / 128, ROWS / 128, 1);

    for (int l = 0; l < LL; l++) {
        long o768  = (long)l * 768 * 768;
        long o256  = (long)l * 768 * 256;
        long o1536 = (long)l * 768 * 1536;
        long oexp  = (long)l * 6 * EXN;

        // ---- attention ----
        rms_kernel<<<ROWS, 256>>>(xp, ln_attn + (long)l * DD, hh, hl);
        gemm3<false, 0><<<gq, 128, GSM>>>(hh, hl, wqh + o768, wql + o768, qp,
                                          nullptr, nullptr, nullptr, ROWS, 768, DD, 0);
        gemm3<false, 0><<<gkv, 128, GSM>>>(hh, hl, wkh + o256, wkl + o256, kp,
                                           wvh + o256, wvl + o256, vp, ROWS, 256, DD, 0);
        attn_kernel<<<dim3(TT / 64, NHH, BB), 64>>>(qp, kp, vp, aoh, aol);
        gemm3<true, 0><<<gq, 128, GSM>>>(aoh, aol, woh + o768, wol + o768, xp,
                                         nullptr, nullptr, nullptr, ROWS, DD, 768, 0);

        // ---- PureField FFN + tension ----
        rms_kernel<<<ROWS, 256>>>(xp, ln_pf + (long)l * DD, hh, hl);
        gemm3<false, 0><<<gff, 128, GSM>>>(hh, hl, pgh + o1536, pgl + o1536, b1p,
                                           puh + o1536, pul + o1536, b2p,
                                           ROWS, DII, DD, 0);
        swiglu_kernel<<<ROWS, 256>>>(b1p, b2p, hdh, hdl, tens + (long)l * ROWS);
        gemm3<true, 0><<<gdn, 128, GSM>>>(hdh, hdl, pdh + (long)l * 1536 * 768,
                                          pdl + (long)l * 1536 * 768, xp,
                                          nullptr, nullptr, nullptr, ROWS, DD, DII, 0);

        // ---- consciousness-state residual (previous layer's tension) ----
        if (l > 0)
            csadd_kernel<<<ROWS, 256>>>(xp, tens + (long)(l - 1) * ROWS, tension_w);

        // ---- MoE ----
        rms_kernel<<<ROWS, 256>>>(xp, ln_moe + (long)l * DD, hh, hl);
        gemm3<false, 1><<<gegu, 128, GSM>>>(hh, hl, egh + oexp, egl + oexp, ebp,
                                            euh + oexp, eul + oexp, nullptr,
                                            ROWS, DII, DD, EXN);
        swiglu_moe_kernel<<<dim3(ROWS, 3), 256>>>(ebp, twp + (long)l * 6, mhh, mhl);
        gemm3<true, 2><<<gdn, 128, GSM>>>(mhh, mhl, edh + oexp, edl + oexp, xp,
                                          nullptr, nullptr, nullptr,
                                          ROWS, DD, DII, EXN);
    }

    // ---- final norm + tied heads (paired) ----
    rms_kernel<<<ROWS, 256>>>(xp, ln_f, hh, hl);
    const dim3 gv(VV / 128, ROWS / 128, 2);
    gemm3<false, 0><<<gv, 128, GSM>>>(hh, hl, emh, eml, out,
                                      hgh, hgl, out + (long)ROWS * VV,
                                      ROWS, VV, DD, 0);
}